// round 6
// baseline (speedup 1.0000x reference)
#include <cuda_runtime.h>
#include <math_constants.h>

// ---------------------------------------------------------------------------
// SinkhornDistillationLoss — GB300 sm_103a
//
// Key structure exploited:
//   C = ones - eye, EPS = 0.05  =>  M[i,j] = 20*(1 - delta_ij) exactly in fp32.
//   logsumexp_j(g_j - M[i,j] + lb_j)
//     = m + log( exp(s_i - m)*(1 - e^-20) + e^-20 * S ),  s = g+lb, S = sum exp(s-m)
//   => Sinkhorn updates are ELEMENTWISE + one per-row max and sum.
//   pi[b,i,j] = u_i * v_j * (i==j ? 1 : e^-20),  u = exp(f+la), v = exp(g+lb)
//   cost_b    = e^-20 * (Su*Sv - sum(u*v))
//
// The reference's early-stop uses a GLOBAL (whole-batch) max err, so all 64
// rows must iterate in lockstep: 64 blocks + software grid barrier.
// ---------------------------------------------------------------------------

#define TPB 256

namespace cfg {
constexpr int B = 64;
constexpr int K = 1000;
constexpr int PERT = 4;          // ceil(1000/256)
constexpr int MAX_ITER = 50;
}

// e^-20 (fp32 nearest)
#define E20_F 2.0611536e-9f
#define THRESH_F 1e-3f
#define CLAMP_MIN_F 1e-8f

// scratch (no allocations allowed)
__device__ float    g_u[cfg::B * cfg::K];
__device__ float    g_v[cfg::B * cfg::K];
__device__ float    g_cost[cfg::B];
__device__ float    g_ce[cfg::B];
__device__ unsigned g_err_bits[cfg::MAX_ITER];
__device__ unsigned g_arrive;

// ---------------------------------------------------------------------------

__global__ void init_kernel() {
    int t = threadIdx.x;
    if (t < cfg::MAX_ITER) g_err_bits[t] = 0u;
    if (t == 0) g_arrive = 0u;
}

// ---------------------------------------------------------------------------

__device__ __forceinline__ float warpMax(float v) {
    #pragma unroll
    for (int o = 16; o; o >>= 1) v = fmaxf(v, __shfl_xor_sync(0xffffffffu, v, o));
    return v;
}
__device__ __forceinline__ float warpSum(float v) {
    #pragma unroll
    for (int o = 16; o; o >>= 1) v += __shfl_xor_sync(0xffffffffu, v, o);
    return v;
}

template <bool IsMax>
__device__ __forceinline__ float blockReduce(float v, float* sh) {
    v = IsMax ? warpMax(v) : warpSum(v);
    int lane = threadIdx.x & 31, w = threadIdx.x >> 5;
    if (lane == 0) sh[w] = v;
    __syncthreads();
    if (threadIdx.x < 32) {
        float x = (threadIdx.x < (TPB / 32)) ? sh[threadIdx.x]
                                             : (IsMax ? -CUDART_INF_F : 0.0f);
        x = IsMax ? warpMax(x) : warpSum(x);
        if (threadIdx.x == 0) sh[0] = x;
    }
    __syncthreads();
    float r = sh[0];
    __syncthreads();
    return r;
}

// grid barrier: 64 blocks are guaranteed co-resident (64 <= 148 SMs)
__device__ __forceinline__ void grid_barrier(unsigned target) {
    __syncthreads();
    if (threadIdx.x == 0) {
        __threadfence();
        atomicAdd(&g_arrive, 1u);
        while (*((volatile unsigned*)&g_arrive) < target) { }
    }
    __syncthreads();
}

// ---------------------------------------------------------------------------
// One block per batch row. All per-row state in registers.
// ---------------------------------------------------------------------------
__global__ __launch_bounds__(TPB, 1)
void sinkhorn_kernel(const float* __restrict__ SL,   // student logits [B,K]
                     const float* __restrict__ TL,   // teacher logits [B,K]
                     const int*   __restrict__ labels) {
    __shared__ float red[32];
    __shared__ float bcast;

    const int b = blockIdx.x;
    const int t = threadIdx.x;
    const float* sl = SL + b * cfg::K;
    const float* tl = TL + b * cfg::K;

    float slr[cfg::PERT], tlr[cfg::PERT];
    bool  valid[cfg::PERT];
    #pragma unroll
    for (int k = 0; k < cfg::PERT; k++) {
        int i = t + k * TPB;
        valid[k] = (i < cfg::K);
        slr[k] = valid[k] ? sl[i] : 0.0f;
        tlr[k] = valid[k] ? tl[i] : 0.0f;
    }

    // ---- CE loss (student, no temperature) ----
    {
        float m = -CUDART_INF_F;
        #pragma unroll
        for (int k = 0; k < cfg::PERT; k++) if (valid[k]) m = fmaxf(m, slr[k]);
        m = blockReduce<true>(m, red);
        float s = 0.0f;
        #pragma unroll
        for (int k = 0; k < cfg::PERT; k++) if (valid[k]) s += expf(slr[k] - m);
        s = blockReduce<false>(s, red);
        if (t == 0) {
            int lab = labels[b];
            g_ce[b] = (m + logf(s)) - sl[lab];   // -log_softmax at label
        }
    }

    // ---- la = log(max(softmax(teacher/4), 1e-8)), lb likewise for student ----
    float la[cfg::PERT], lb[cfg::PERT];
    {
        float m = -CUDART_INF_F;
        #pragma unroll
        for (int k = 0; k < cfg::PERT; k++) {
            float y = tlr[k] * 0.25f; la[k] = y;
            if (valid[k]) m = fmaxf(m, y);
        }
        m = blockReduce<true>(m, red);
        float s = 0.0f;
        #pragma unroll
        for (int k = 0; k < cfg::PERT; k++) if (valid[k]) s += expf(la[k] - m);
        s = blockReduce<false>(s, red);
        #pragma unroll
        for (int k = 0; k < cfg::PERT; k++) {
            float p = expf(la[k] - m) / s;
            la[k] = logf(fmaxf(p, CLAMP_MIN_F));
        }
    }
    {
        float m = -CUDART_INF_F;
        #pragma unroll
        for (int k = 0; k < cfg::PERT; k++) {
            float y = slr[k] * 0.25f; lb[k] = y;
            if (valid[k]) m = fmaxf(m, y);
        }
        m = blockReduce<true>(m, red);
        float s = 0.0f;
        #pragma unroll
        for (int k = 0; k < cfg::PERT; k++) if (valid[k]) s += expf(lb[k] - m);
        s = blockReduce<false>(s, red);
        #pragma unroll
        for (int k = 0; k < cfg::PERT; k++) {
            float p = expf(lb[k] - m) / s;
            lb[k] = logf(fmaxf(p, CLAMP_MIN_F));
        }
    }

    // ---- Sinkhorn iterations (lockstep across batch via grid barrier) ----
    float f[cfg::PERT], g[cfg::PERT];
    #pragma unroll
    for (int k = 0; k < cfg::PERT; k++) { f[k] = 0.0f; g[k] = 0.0f; }

    const float C1 = 1.0f - E20_F;

    for (int it = 0; it < cfg::MAX_ITER; ++it) {
        // f-update: s_i = g_i + lb_i
        float m1 = -CUDART_INF_F;
        #pragma unroll
        for (int k = 0; k < cfg::PERT; k++) if (valid[k]) m1 = fmaxf(m1, g[k] + lb[k]);
        m1 = blockReduce<true>(m1, red);
        float S1 = 0.0f;
        #pragma unroll
        for (int k = 0; k < cfg::PERT; k++) if (valid[k]) S1 += expf(g[k] + lb[k] - m1);
        S1 = blockReduce<false>(S1, red);

        float err = 0.0f;
        #pragma unroll
        for (int k = 0; k < cfg::PERT; k++) {
            if (valid[k]) {
                float si = g[k] + lb[k];
                float fn = -(m1 + logf(expf(si - m1) * C1 + E20_F * S1));
                err = fmaxf(err, fabsf(fn - f[k]));
                f[k] = fn;
            }
        }
        err = blockReduce<true>(err, red);

        // g-update: t_i = f_i + la_i
        float m2 = -CUDART_INF_F;
        #pragma unroll
        for (int k = 0; k < cfg::PERT; k++) if (valid[k]) m2 = fmaxf(m2, f[k] + la[k]);
        m2 = blockReduce<true>(m2, red);
        float S2 = 0.0f;
        #pragma unroll
        for (int k = 0; k < cfg::PERT; k++) if (valid[k]) S2 += expf(f[k] + la[k] - m2);
        S2 = blockReduce<false>(S2, red);
        #pragma unroll
        for (int k = 0; k < cfg::PERT; k++) {
            if (valid[k]) {
                float ti = f[k] + la[k];
                g[k] = -(m2 + logf(expf(ti - m2) * C1 + E20_F * S2));
            }
        }

        // global (whole-batch) convergence check — matches reference semantics
        if (t == 0) atomicMax(&g_err_bits[it], __float_as_uint(err));
        grid_barrier((unsigned)(it + 1) * cfg::B);
        if (t == 0) bcast = __uint_as_float(*((volatile unsigned*)&g_err_bits[it]));
        __syncthreads();
        if (bcast < THRESH_F) break;
    }

    // ---- u, v, per-row cost ----
    float Su = 0.0f, Sv = 0.0f, Suv = 0.0f;
    #pragma unroll
    for (int k = 0; k < cfg::PERT; k++) {
        if (valid[k]) {
            float u = expf(f[k] + la[k]);
            float v = expf(g[k] + lb[k]);
            int i = t + k * TPB;
            g_u[b * cfg::K + i] = u;
            g_v[b * cfg::K + i] = v;
            Su += u; Sv += v; Suv += u * v;
        }
    }
    Su  = blockReduce<false>(Su, red);
    Sv  = blockReduce<false>(Sv, red);
    Suv = blockReduce<false>(Suv, red);
    if (t == 0) g_cost[b] = E20_F * (Su * Sv - Suv);
}

// ---------------------------------------------------------------------------
// Transport plan writer: pi[b,i,j] = u_i * v_j * (i==j ? 1 : e^-20)
// One block per (b,i) row; 256 MB of stores — HBM bound.
// ---------------------------------------------------------------------------
__global__ __launch_bounds__(256)
void plan_kernel(float* __restrict__ out) {
    const int i = blockIdx.x;
    const int b = blockIdx.y;
    const float u = __ldg(&g_u[b * cfg::K + i]);
    const float* __restrict__ vrow = &g_v[b * cfg::K];
    float* __restrict__ o = out + 3 + ((size_t)(b * cfg::K + i)) * cfg::K;

    #pragma unroll 4
    for (int j = threadIdx.x; j < cfg::K; j += 256) {
        float val = u * __ldg(&vrow[j]);
        o[j] = (j == i) ? val : val * E20_F;
    }
}

// ---------------------------------------------------------------------------

__global__ void finalize_kernel(float* __restrict__ out) {
    if (threadIdx.x == 0) {
        float sc = 0.0f, se = 0.0f;
        for (int b = 0; b < cfg::B; b++) { sc += g_cost[b]; se += g_ce[b]; }
        float ot = sc / (float)cfg::B;
        float ce = se / (float)cfg::B;
        out[0] = ce + 0.5f * ot;   // total_loss
        out[1] = ot;               // ot_loss
        out[2] = ce;               // ce_loss
    }
}

// ---------------------------------------------------------------------------

extern "C" void kernel_launch(void* const* d_in, const int* in_sizes, int n_in,
                              void* d_out, int out_size) {
    const float* SL     = (const float*)d_in[0];   // student_logits [64,1000]
    const float* TL     = (const float*)d_in[1];   // teacher_logits [64,1000]
    const int*   labels = (const int*)d_in[2];     // labels [64]
    // d_in[3] = C, structure known analytically (ones - eye): unused.
    float* out = (float*)d_out;

    init_kernel<<<1, 64>>>();
    sinkhorn_kernel<<<cfg::B, TPB>>>(SL, TL, labels);
    dim3 pg(cfg::K, cfg::B);
    plan_kernel<<<pg, 256>>>(out);
    finalize_kernel<<<1, 32>>>(out);
}

// round 11
// speedup vs baseline: 1.2083x; 1.2083x over previous
#include <cuda_runtime.h>
#include <math_constants.h>

// ---------------------------------------------------------------------------
// SinkhornDistillationLoss — GB300 sm_103a
//
// C = ones - eye, EPS = 0.05  =>  M[i,j] = 20*(1 - delta_ij) exactly in fp32.
//   lse_j(g_j - M[i,j] + lb_j) = log( exp(s_i)*(1-e^-20) + e^-20 * S ),
//     s = g+lb, S = sum_j exp(s_j)        (no max-subtraction: |f|,|g| <~ 20)
//   pi[b,i,j] = u_i * v_j * (i==j ? 1 : e^-20),  u = exp(f+la), v = exp(g+lb)
//   cost_b    = e^-20 * (Su*Sv - sum(u*v))
//
// Reference early-stop: a single GLOBAL done flag => all rows run exactly
//   NITER = t*+1 iterations, t* = first t with max_b err_b(t) < THRESH.
// Up to t*, rows evolve independently => run each row 50 iters with NO
// inter-block sync, snapshot (u_t, v_t) every iteration, pick t* afterwards.
// ---------------------------------------------------------------------------

#define TPB 256

namespace cfg {
constexpr int B = 64;
constexpr int K = 1000;
constexpr int PERT = 4;          // 1000 / 256 rounded up
constexpr int MAX_ITER = 50;
}

#define E20_F 2.0611536e-9f      // e^-20, fp32 nearest
#define THRESH_F 1e-3f
#define CLAMP_MIN_F 1e-8f

// scratch (static device globals; no allocations allowed)
__device__ float g_err [cfg::MAX_ITER][cfg::B];
__device__ float g_usnap[cfg::MAX_ITER][cfg::B][cfg::K];   // 12.8 MB
__device__ float g_vsnap[cfg::MAX_ITER][cfg::B][cfg::K];   // 12.8 MB
__device__ int   g_tstar;
__device__ float g_cost[cfg::B];
__device__ float g_ce  [cfg::B];

// ---------------------------------------------------------------------------

__device__ __forceinline__ float warpMax(float v) {
    #pragma unroll
    for (int o = 16; o; o >>= 1) v = fmaxf(v, __shfl_xor_sync(0xffffffffu, v, o));
    return v;
}
__device__ __forceinline__ float warpSum(float v) {
    #pragma unroll
    for (int o = 16; o; o >>= 1) v += __shfl_xor_sync(0xffffffffu, v, o);
    return v;
}

template <bool IsMax>
__device__ __forceinline__ float blockReduce(float v, float* sh) {
    v = IsMax ? warpMax(v) : warpSum(v);
    int lane = threadIdx.x & 31, w = threadIdx.x >> 5;
    if (lane == 0) sh[w] = v;
    __syncthreads();
    if (threadIdx.x < 32) {
        float x = (threadIdx.x < (TPB / 32)) ? sh[threadIdx.x]
                                             : (IsMax ? -CUDART_INF_F : 0.0f);
        x = IsMax ? warpMax(x) : warpSum(x);
        if (threadIdx.x == 0) sh[0] = x;
    }
    __syncthreads();
    float r = sh[0];
    __syncthreads();
    return r;
}

// fused sum + max reduction: one barrier round for both
__device__ __forceinline__ void blockReduceSumMax(float& sv, float& mv,
                                                  float* shs, float* shm) {
    sv = warpSum(sv);
    mv = warpMax(mv);
    int lane = threadIdx.x & 31, w = threadIdx.x >> 5;
    if (lane == 0) { shs[w] = sv; shm[w] = mv; }
    __syncthreads();
    if (threadIdx.x < 32) {
        float s = (threadIdx.x < (TPB / 32)) ? shs[threadIdx.x] : 0.0f;
        float m = (threadIdx.x < (TPB / 32)) ? shm[threadIdx.x] : -CUDART_INF_F;
        s = warpSum(s);
        m = warpMax(m);
        if (threadIdx.x == 0) { shs[0] = s; shm[0] = m; }
    }
    __syncthreads();
    sv = shs[0];
    mv = shm[0];
    __syncthreads();
}

// ---------------------------------------------------------------------------
// Pass 1: one block per batch row, fully independent. 50 iterations, per-iter
// err + (u,v) snapshots to global. All per-row state in registers.
// ---------------------------------------------------------------------------
__global__ __launch_bounds__(TPB, 1)
void sinkhorn_iter_kernel(const float* __restrict__ SL,
                          const float* __restrict__ TL,
                          const int*   __restrict__ labels) {
    __shared__ float red[8];
    __shared__ float red2[8];

    const int b = blockIdx.x;
    const int t = threadIdx.x;
    const float* sl = SL + b * cfg::K;
    const float* tl = TL + b * cfg::K;

    float slr[cfg::PERT], tlr[cfg::PERT];
    bool  valid[cfg::PERT];
    #pragma unroll
    for (int k = 0; k < cfg::PERT; k++) {
        int i = t + k * TPB;
        valid[k] = (i < cfg::K);
        slr[k] = valid[k] ? sl[i] : 0.0f;
        tlr[k] = valid[k] ? tl[i] : 0.0f;
    }

    // ---- CE loss (student, no temperature) ----
    {
        float m = -CUDART_INF_F;
        #pragma unroll
        for (int k = 0; k < cfg::PERT; k++) if (valid[k]) m = fmaxf(m, slr[k]);
        m = blockReduce<true>(m, red);
        float s = 0.0f;
        #pragma unroll
        for (int k = 0; k < cfg::PERT; k++) if (valid[k]) s += expf(slr[k] - m);
        s = blockReduce<false>(s, red);
        if (t == 0) {
            int lab = labels[b];
            g_ce[b] = (m + logf(s)) - sl[lab];
        }
    }

    // ---- la = log(max(softmax(teacher/4), 1e-8)), lb from student ----
    float la[cfg::PERT], lb[cfg::PERT];
    {
        float m = -CUDART_INF_F;
        #pragma unroll
        for (int k = 0; k < cfg::PERT; k++) {
            float y = tlr[k] * 0.25f; la[k] = y;
            if (valid[k]) m = fmaxf(m, y);
        }
        m = blockReduce<true>(m, red);
        float s = 0.0f;
        #pragma unroll
        for (int k = 0; k < cfg::PERT; k++) if (valid[k]) s += expf(la[k] - m);
        s = blockReduce<false>(s, red);
        #pragma unroll
        for (int k = 0; k < cfg::PERT; k++) {
            float p = expf(la[k] - m) / s;
            la[k] = logf(fmaxf(p, CLAMP_MIN_F));
        }
    }
    {
        float m = -CUDART_INF_F;
        #pragma unroll
        for (int k = 0; k < cfg::PERT; k++) {
            float y = slr[k] * 0.25f; lb[k] = y;
            if (valid[k]) m = fmaxf(m, y);
        }
        m = blockReduce<true>(m, red);
        float s = 0.0f;
        #pragma unroll
        for (int k = 0; k < cfg::PERT; k++) if (valid[k]) s += expf(lb[k] - m);
        s = blockReduce<false>(s, red);
        #pragma unroll
        for (int k = 0; k < cfg::PERT; k++) {
            float p = expf(lb[k] - m) / s;
            lb[k] = logf(fmaxf(p, CLAMP_MIN_F));
        }
    }

    // ---- 50 unfrozen Sinkhorn iterations, snapshot u_t, v_t ----
    float f[cfg::PERT], g[cfg::PERT];
    #pragma unroll
    for (int k = 0; k < cfg::PERT; k++) { f[k] = 0.0f; g[k] = 0.0f; }

    const float C1 = 1.0f - E20_F;

    for (int it = 0; it < cfg::MAX_ITER; ++it) {
        // f-update: e = exp(g + lb) = v_{it-1}
        float e[cfg::PERT];
        float S1 = 0.0f;
        #pragma unroll
        for (int k = 0; k < cfg::PERT; k++) {
            e[k] = valid[k] ? expf(g[k] + lb[k]) : 0.0f;
            S1 += e[k];
        }
        S1 = blockReduce<false>(S1, red);

        if (it > 0) {
            float* __restrict__ vs = &g_vsnap[it - 1][b][0];
            #pragma unroll
            for (int k = 0; k < cfg::PERT; k++)
                if (valid[k]) vs[t + k * TPB] = e[k];
        }

        float err = 0.0f;
        #pragma unroll
        for (int k = 0; k < cfg::PERT; k++) {
            if (valid[k]) {
                float fn = -logf(fmaf(e[k], C1, E20_F * S1));
                err = fmaxf(err, fabsf(fn - f[k]));
                f[k] = fn;
            }
        }

        // g-update: u = exp(f + la) = u_it ; fused (sum, max) reduction
        float u[cfg::PERT];
        float S2 = 0.0f;
        #pragma unroll
        for (int k = 0; k < cfg::PERT; k++) {
            u[k] = valid[k] ? expf(f[k] + la[k]) : 0.0f;
            S2 += u[k];
        }
        blockReduceSumMax(S2, err, red, red2);

        {
            float* __restrict__ us = &g_usnap[it][b][0];
            #pragma unroll
            for (int k = 0; k < cfg::PERT; k++)
                if (valid[k]) us[t + k * TPB] = u[k];
        }

        #pragma unroll
        for (int k = 0; k < cfg::PERT; k++)
            if (valid[k]) g[k] = -logf(fmaf(u[k], C1, E20_F * S2));

        if (t == 0) g_err[it][b] = err;   // unique slot — no atomic
    }

    // final v snapshot: v_49 = exp(g_49 + lb)
    {
        float* __restrict__ vs = &g_vsnap[cfg::MAX_ITER - 1][b][0];
        #pragma unroll
        for (int k = 0; k < cfg::PERT; k++)
            if (valid[k]) vs[t + k * TPB] = expf(g[k] + lb[k]);
    }
}

// ---------------------------------------------------------------------------
// Pick t* = first t with max_b err[t][b] < THRESH (else MAX_ITER-1).
// ---------------------------------------------------------------------------
__global__ void combine_kernel() {
    __shared__ int flags[cfg::MAX_ITER];
    int t = threadIdx.x;
    if (t < cfg::MAX_ITER) {
        float m = 0.0f;
        #pragma unroll 4
        for (int b = 0; b < cfg::B; b++) m = fmaxf(m, g_err[t][b]);
        flags[t] = (m < THRESH_F) ? 1 : 0;
    }
    __syncthreads();
    if (t == 0) {
        int ts = cfg::MAX_ITER - 1;
        for (int i = 0; i < cfg::MAX_ITER; i++)
            if (flags[i]) { ts = i; break; }
        g_tstar = ts;
    }
}

// ---------------------------------------------------------------------------
// Per-row OT cost from snapshot t*: cost_b = e^-20 * (Su*Sv - sum(u*v))
// ---------------------------------------------------------------------------
__global__ __launch_bounds__(TPB)
void cost_kernel() {
    __shared__ float red[8];
    const int b = blockIdx.x;
    const int t = threadIdx.x;
    const int ts = g_tstar;
    const float* __restrict__ u = &g_usnap[ts][b][0];
    const float* __restrict__ v = &g_vsnap[ts][b][0];

    float Su = 0.0f, Sv = 0.0f, Suv = 0.0f;
    for (int i = t; i < cfg::K; i += TPB) {
        float uu = u[i], vv = v[i];
        Su += uu; Sv += vv; Suv += uu * vv;
    }
    Su  = blockReduce<false>(Su,  red);
    Sv  = blockReduce<false>(Sv,  red);
    Suv = blockReduce<false>(Suv, red);
    if (t == 0) g_cost[b] = E20_F * (Su * Sv - Suv);
}

// ---------------------------------------------------------------------------
// Transport plan: pi[b,i,j] = u_i * v_j * (i==j ? 1 : e^-20).
// 8 rows per block (1000 = 125*8), v and v*e^-20 staged in smem.
// 256 MB of coalesced stores — HBM bound.
// ---------------------------------------------------------------------------
#define PLAN_R 8
__global__ __launch_bounds__(256)
void plan_kernel(float* __restrict__ out) {
    __shared__ float sv [cfg::K];
    __shared__ float sv2[cfg::K];
    __shared__ float su [PLAN_R];

    const int b  = blockIdx.y;
    const int i0 = blockIdx.x * PLAN_R;
    const int t  = threadIdx.x;
    const int ts = g_tstar;
    const float* __restrict__ ub = &g_usnap[ts][b][0];
    const float* __restrict__ vb = &g_vsnap[ts][b][0];

    for (int j = t; j < cfg::K; j += 256) {
        float v = vb[j];
        sv[j]  = v;
        sv2[j] = v * E20_F;
    }
    if (t < PLAN_R) su[t] = ub[i0 + t];
    __syncthreads();

    #pragma unroll
    for (int r = 0; r < PLAN_R; r++) {
        const int i = i0 + r;
        const float u    = su[r];
        const float diag = u * sv[i];
        float* __restrict__ o = out + 3 + (size_t)(b * cfg::K + i) * cfg::K;
        #pragma unroll 4
        for (int j = t; j < cfg::K; j += 256)
            o[j] = (j == i) ? diag : u * sv2[j];
    }
}

// ---------------------------------------------------------------------------

__global__ void finalize_kernel(float* __restrict__ out) {
    int t = threadIdx.x;                      // 32 threads, 2 rows each
    float sc = g_cost[t] + g_cost[t + 32];
    float se = g_ce[t]   + g_ce[t + 32];
    sc = warpSum(sc);
    se = warpSum(se);
    if (t == 0) {
        float ot = sc / (float)cfg::B;
        float ce = se / (float)cfg::B;
        out[0] = ce + 0.5f * ot;   // total_loss
        out[1] = ot;               // ot_loss
        out[2] = ce;               // ce_loss
    }
}

// ---------------------------------------------------------------------------

extern "C" void kernel_launch(void* const* d_in, const int* in_sizes, int n_in,
                              void* d_out, int out_size) {
    const float* SL     = (const float*)d_in[0];   // student_logits [64,1000]
    const float* TL     = (const float*)d_in[1];   // teacher_logits [64,1000]
    const int*   labels = (const int*)d_in[2];     // labels [64]
    // d_in[3] = C, known analytically (ones - eye): unused.
    float* out = (float*)d_out;

    sinkhorn_iter_kernel<<<cfg::B, TPB>>>(SL, TL, labels);
    combine_kernel<<<1, 64>>>();
    cost_kernel<<<cfg::B, TPB>>>();
    dim3 pg(cfg::K / PLAN_R, cfg::B);
    plan_kernel<<<pg, 256>>>(out);
    finalize_kernel<<<1, 32>>>(out);
}